// round 10
// baseline (speedup 1.0000x reference)
#include <cuda_runtime.h>
#include <cuda_bf16.h>
#include <cuda_fp16.h>
#include <cstdint>

#define NN      8192
#define F_IN    512
#define NOUT    64
#define LRA     0.2f
#define JSPLITS 8
#define JLEN    (NN / JSPLITS)     // 1024
#define NCH     (JLEN / 16)        // 64 chunks of k=16
#define NBLK    (NCH / 2)          // 32 blocks of k=32
#define BST     80                 // padded bytes per n-row in staged B
#define BBUF    (64 * BST)         // 5120 B per stage

// ---------------- device scratch (no cudaMalloc allowed) -------------------
__device__ uint4 g_W_pk[64 * 32 * 4];                  // 128 KB (bf16 frags, wh GEMM)
__device__ __align__(16) __half g_WhT_hi[NOUT * NN];   // fp16 Wh^T, [n][j]
__device__ float g_e1[NN];
__device__ float g_e2[NN];
__device__ float g_m2;                                 // max_j e2[j]
__device__ float g_pacc[JSPLITS][NN][NOUT];
__device__ float g_pden[JSPLITS][NN];

// ---------------- helpers ---------------------------------------------------
__device__ __forceinline__ void mma_bf16(float* d, const unsigned* a,
                                         unsigned b0, unsigned b1) {
    asm volatile(
        "mma.sync.aligned.m16n8k16.row.col.f32.bf16.bf16.f32 "
        "{%0,%1,%2,%3}, {%4,%5,%6,%7}, {%8,%9}, {%0,%1,%2,%3};"
        : "+f"(d[0]), "+f"(d[1]), "+f"(d[2]), "+f"(d[3])
        : "r"(a[0]), "r"(a[1]), "r"(a[2]), "r"(a[3]), "r"(b0), "r"(b1));
}
__device__ __forceinline__ void mma_f16(float* d, const unsigned* a,
                                        unsigned b0, unsigned b1) {
    asm volatile(
        "mma.sync.aligned.m16n8k16.row.col.f32.f16.f16.f32 "
        "{%0,%1,%2,%3}, {%4,%5,%6,%7}, {%8,%9}, {%0,%1,%2,%3};"
        : "+f"(d[0]), "+f"(d[1]), "+f"(d[2]), "+f"(d[3])
        : "r"(a[0]), "r"(a[1]), "r"(a[2]), "r"(a[3]), "r"(b0), "r"(b1));
}
__device__ __forceinline__ void ldsm4(unsigned* r, uint32_t addr) {
    asm volatile("ldmatrix.sync.aligned.m8n8.x4.shared.b16 {%0,%1,%2,%3}, [%4];"
                 : "=r"(r[0]), "=r"(r[1]), "=r"(r[2]), "=r"(r[3]) : "r"(addr));
}
__device__ __forceinline__ unsigned cvt2b(float po, float pe) {  // bf16x2, lo=pe
    unsigned r;
    asm("cvt.rn.bf16x2.f32 %0, %1, %2;" : "=r"(r) : "f"(po), "f"(pe));
    return r;
}
__device__ __forceinline__ unsigned cvt2h(float po, float pe) {  // f16x2, lo=pe
    unsigned r;
    asm("cvt.rn.f16x2.f32 %0, %1, %2;" : "=r"(r) : "f"(po), "f"(pe));
    return r;
}
__device__ __forceinline__ float bfhf(float x) {
    return __bfloat162float(__float2bfloat16_rn(x));
}
__device__ __forceinline__ uint32_t smem_u32(const void* p) {
    return (uint32_t)__cvta_generic_to_shared(p);
}
__device__ __forceinline__ void cpa16(uint32_t dst, const void* src) {
    asm volatile("cp.async.cg.shared.global [%0], [%1], 16;" :: "r"(dst), "l"(src));
}
__device__ __forceinline__ void cpcommit() {
    asm volatile("cp.async.commit_group;" ::: "memory");
}
template <int N> __device__ __forceinline__ void cpwait() {
    asm volatile("cp.async.wait_group %0;" :: "n"(N) : "memory");
}

// ---------------------------------------------------------------------------
// Kernel 0: pack W (fp32 [512][64]) into bf16 hi/lo fragment layout (wh GEMM).
// ---------------------------------------------------------------------------
__global__ void __launch_bounds__(256) prep_w(const float* __restrict__ W) {
    const int t = blockIdx.x * 256 + threadIdx.x;
    const int s = t & 3, kc = (t >> 2) & 31, n = t >> 7;
    const int k0 = kc * 16 + 2 * s;
    float v00 = W[(k0 + 0) * 64 + n], v01 = W[(k0 + 1) * 64 + n];
    float v10 = W[(k0 + 8) * 64 + n], v11 = W[(k0 + 9) * 64 + n];
    float h00 = bfhf(v00), h01 = bfhf(v01), h10 = bfhf(v10), h11 = bfhf(v11);
    uint4 o;
    o.x = cvt2b(h01, h00);
    o.y = cvt2b(h11, h10);
    o.z = cvt2b(v01 - h01, v00 - h00);
    o.w = cvt2b(v11 - h11, v10 - h10);
    g_W_pk[(n * 32 + kc) * 4 + s] = o;
}

// ---------------------------------------------------------------------------
// Kernel 1: Wh = h @ W via mma.sync (3-product bf16 split; accurate e1/e2).
// Epilogue: e1/e2, WhT packed as fp16 row-major [n][j].
// ---------------------------------------------------------------------------
__global__ void __launch_bounds__(128, 1) wh_mma(const float* __restrict__ h,
                                                 const float* __restrict__ a) {
    __shared__ float s_h[3][64][20];
    __shared__ float s_t[64][65];

    const int tid = threadIdx.x;
    const int w = tid >> 5;
    const int l = tid & 31;
    const int r = l >> 2;
    const int c = (l & 3) * 2;
    const int node0 = blockIdx.x * 64;

    const uint32_t shb = smem_u32(&s_h[0][0][0]);
    auto stage = [&](int kc, int s) {
        const int row = tid >> 1, half = tid & 1;
        const float* src = h + (size_t)(node0 + row) * F_IN + kc * 16 + half * 8;
        uint32_t dst = shb + (uint32_t)((s * 64 + row) * 20 + half * 8) * 4;
        cpa16(dst, src);
        cpa16(dst + 16, src + 4);
    };

    stage(0, 0); cpcommit();
    stage(1, 1); cpcommit();

    float acc[8][4];
#pragma unroll
    for (int n = 0; n < 8; ++n)
#pragma unroll
        for (int q = 0; q < 4; ++q) acc[n][q] = 0.f;

    const uint4* __restrict__ wpk = g_W_pk;

    for (int kc = 0; kc < 32; ++kc) {
        const int ss = kc % 3;
        if (kc + 1 < 32) cpwait<1>(); else cpwait<0>();
        __syncthreads();
        if (kc + 2 < 32) { stage(kc + 2, (kc + 2) % 3); cpcommit(); }

        uint4 B4[8];
#pragma unroll
        for (int nt = 0; nt < 8; ++nt)
            B4[nt] = wpk[((nt * 8 + r) * 32 + kc) * 4 + (l & 3)];

        float2 v0 = *(const float2*)&s_h[ss][w * 16 + r][c];
        float2 v1 = *(const float2*)&s_h[ss][w * 16 + r + 8][c];
        float2 v2 = *(const float2*)&s_h[ss][w * 16 + r][c + 8];
        float2 v3 = *(const float2*)&s_h[ss][w * 16 + r + 8][c + 8];
        float h0x = bfhf(v0.x), h0y = bfhf(v0.y);
        float h1x = bfhf(v1.x), h1y = bfhf(v1.y);
        float h2x = bfhf(v2.x), h2y = bfhf(v2.y);
        float h3x = bfhf(v3.x), h3y = bfhf(v3.y);
        unsigned Ah[4], Al[4];
        Ah[0] = cvt2b(h0y, h0x); Al[0] = cvt2b(v0.y - h0y, v0.x - h0x);
        Ah[1] = cvt2b(h1y, h1x); Al[1] = cvt2b(v1.y - h1y, v1.x - h1x);
        Ah[2] = cvt2b(h2y, h2x); Al[2] = cvt2b(v2.y - h2y, v2.x - h2x);
        Ah[3] = cvt2b(h3y, h3x); Al[3] = cvt2b(v3.y - h3y, v3.x - h3x);

#pragma unroll
        for (int nt = 0; nt < 8; ++nt) mma_bf16(acc[nt], Ah, B4[nt].x, B4[nt].y);
#pragma unroll
        for (int nt = 0; nt < 8; ++nt) mma_bf16(acc[nt], Al, B4[nt].x, B4[nt].y);
#pragma unroll
        for (int nt = 0; nt < 8; ++nt) mma_bf16(acc[nt], Ah, B4[nt].z, B4[nt].w);
    }

    {
        float e1p0 = 0.f, e1p8 = 0.f, e2p0 = 0.f, e2p8 = 0.f;
#pragma unroll
        for (int nt = 0; nt < 8; ++nt) {
            float2 a1v = *(const float2*)&a[nt * 8 + c];
            float2 a2v = *(const float2*)&a[NOUT + nt * 8 + c];
            e1p0 += acc[nt][0] * a1v.x + acc[nt][1] * a1v.y;
            e1p8 += acc[nt][2] * a1v.x + acc[nt][3] * a1v.y;
            e2p0 += acc[nt][0] * a2v.x + acc[nt][1] * a2v.y;
            e2p8 += acc[nt][2] * a2v.x + acc[nt][3] * a2v.y;
        }
#pragma unroll
        for (int off = 1; off <= 2; off <<= 1) {
            e1p0 += __shfl_xor_sync(0xffffffffu, e1p0, off);
            e1p8 += __shfl_xor_sync(0xffffffffu, e1p8, off);
            e2p0 += __shfl_xor_sync(0xffffffffu, e2p0, off);
            e2p8 += __shfl_xor_sync(0xffffffffu, e2p8, off);
        }
        if ((l & 3) == 0) {
            g_e1[node0 + w * 16 + r]     = e1p0;
            g_e1[node0 + w * 16 + r + 8] = e1p8;
            g_e2[node0 + w * 16 + r]     = e2p0;
            g_e2[node0 + w * 16 + r + 8] = e2p8;
        }
    }

    __syncthreads();
#pragma unroll
    for (int nt = 0; nt < 8; ++nt) {
        s_t[w * 16 + r][nt * 8 + c]         = acc[nt][0];
        s_t[w * 16 + r][nt * 8 + c + 1]     = acc[nt][1];
        s_t[w * 16 + r + 8][nt * 8 + c]     = acc[nt][2];
        s_t[w * 16 + r + 8][nt * 8 + c + 1] = acc[nt][3];
    }
    __syncthreads();

    // pack WhT as fp16: thread -> (col n, half nh), 32 j's contiguous
    {
        const int col = tid >> 1, nh = tid & 1;
        float f[32];
#pragma unroll
        for (int j = 0; j < 32; ++j) f[j] = s_t[nh * 32 + j][col];
        unsigned hw[16];
#pragma unroll
        for (int q = 0; q < 16; ++q) hw[q] = cvt2h(f[2 * q + 1], f[2 * q]);
        const size_t base = (size_t)col * NN + blockIdx.x * 64 + nh * 32;
        uint4* dh = (uint4*)(g_WhT_hi + base);
#pragma unroll
        for (int q = 0; q < 4; ++q) dh[q] = *(uint4*)&hw[4 * q];
    }
}

// ---------------------------------------------------------------------------
// Kernel 1.5: global max of e2 (single CTA).
// ---------------------------------------------------------------------------
__global__ void __launch_bounds__(256) e2max_kernel() {
    __shared__ float sm[8];
    const int tid = threadIdx.x;
    float m = -1e30f;
    for (int k = tid; k < NN; k += 256) m = fmaxf(m, g_e2[k]);
#pragma unroll
    for (int off = 16; off; off >>= 1)
        m = fmaxf(m, __shfl_xor_sync(0xffffffffu, m, off));
    if ((tid & 31) == 0) sm[tid >> 5] = m;
    __syncthreads();
    if (tid == 0) {
        float mm = sm[0];
#pragma unroll
        for (int q = 1; q < 8; ++q) mm = fmaxf(mm, sm[q]);
        g_m2 = mm;
    }
}

// ---------------------------------------------------------------------------
// Kernel 2: fused masked-exp + single-product fp16 GEMM via mma.sync.
// p = exp(lrelu(e1+e2) - M_i) in (0,1] (fp16 A); Wh fp16 (B). 8 HMMA/chunk.
// 3 CTAs/SM (wave: 512 = 444+68); B via 3-stage cp.async + ldmatrix.
// ---------------------------------------------------------------------------
__global__ void __launch_bounds__(256, 3) attn_kernel(const int* __restrict__ adj) {
    __shared__ float s_e2[JLEN];                      // 4 KB
    __shared__ __align__(16) char s_B[3][BBUF];       // 15 KB

    const int tid = threadIdx.x;
    const int w = tid >> 5;
    const int l = tid & 31;
    const int i0 = (int)(blockIdx.x >> 3) * 128;
    const int split = blockIdx.x & 7;
    const int j0 = split * JLEN;

    {
        float4* d = (float4*)s_e2;
        const float4* s = (const float4*)(g_e2 + j0);
        for (int k = tid; k < JLEN / 4; k += 256) d[k] = s[k];
    }

    const int rq = l >> 2;          // 0..7
    const int cq = (l & 3) * 2;     // 0,2,4,6
    const float M2 = g_m2;

    float e1r[2], mi[2];
    const int* rb[2];
#pragma unroll
    for (int k = 0; k < 2; ++k) {
        int row = i0 + w * 16 + 8 * k + rq;
        e1r[k] = g_e1[row];
        float mv = e1r[k] + M2;
        mi[k] = mv > 0.f ? mv : LRA * mv;   // row max logit
        rb[k] = adj + (size_t)row * NN + j0 + cq;
    }

    const uint32_t sBs = smem_u32(&s_B[0][0]);
    // B hi tile for block blk: 64n x 32k fp16 = 4KB = one cpa16 per thread
    auto stage = [&](int blk, int s) {
        const int c = tid >> 6;              // 16B chunk 0..3 (8 halves)
        const int n = tid & 63;              // n-row
        const __half* src = g_WhT_hi + (size_t)n * NN + j0 + blk * 32 + c * 8;
        cpa16(sBs + (uint32_t)(s * BBUF + n * BST + c * 16), src);
    };

    const int g = l >> 3, lr = l & 7;
    const uint32_t sBm = sBs + (uint32_t)((lr + ((g >> 1) << 3)) * BST + ((g & 1) << 4));

    float acc[8][4];
#pragma unroll
    for (int n = 0; n < 8; ++n)
#pragma unroll
        for (int q = 0; q < 4; ++q) acc[n][q] = 0.f;
    float den2[2] = {0.f, 0.f};

    stage(0, 0); cpcommit();
    stage(1, 1); cpcommit();
    int2 alo[2], ahi[2];
#pragma unroll
    for (int k = 0; k < 2; ++k) {
        alo[k] = *(const int2*)(rb[k]);
        ahi[k] = *(const int2*)(rb[k] + 8);
    }

    for (int blk = 0; blk < NBLK; ++blk) {
        const int s = blk % 3;
        if (blk + 1 < NBLK) cpwait<1>(); else cpwait<0>();
        __syncthreads();
        if (blk + 2 < NBLK) { stage(blk + 2, (blk + 2) % 3); cpcommit(); }

#pragma unroll
        for (int c2 = 0; c2 < 2; ++c2) {
            const int ch = blk * 2 + c2;

            // ---- A fragments: shifted masked exp, fp16 ----
            const float* e2p = s_e2 + ch * 16;
            float2 e2a = *(const float2*)(e2p + cq);
            float2 e2b = *(const float2*)(e2p + cq + 8);
            unsigned Ah[4];
#pragma unroll
            for (int k = 0; k < 2; ++k) {
                const float e1v = e1r[k];
                float s0 = e1v + e2a.x; s0 = (s0 > 0.f ? s0 : LRA * s0) - mi[k];
                float s1 = e1v + e2a.y; s1 = (s1 > 0.f ? s1 : LRA * s1) - mi[k];
                float s2 = e1v + e2b.x; s2 = (s2 > 0.f ? s2 : LRA * s2) - mi[k];
                float s3 = e1v + e2b.y; s3 = (s3 > 0.f ? s3 : LRA * s3) - mi[k];
                float p0 = alo[k].x > 0 ? __expf(s0) : 0.f;
                float p1 = alo[k].y > 0 ? __expf(s1) : 0.f;
                float p2 = ahi[k].x > 0 ? __expf(s2) : 0.f;
                float p3 = ahi[k].y > 0 ? __expf(s3) : 0.f;
                den2[k] += (p0 + p1) + (p2 + p3);
                Ah[k]     = cvt2h(p1, p0);
                Ah[k + 2] = cvt2h(p3, p2);
            }

            // ---- prefetch next chunk's adj ----
            if (ch + 1 < NCH) {
#pragma unroll
                for (int k = 0; k < 2; ++k) {
                    alo[k] = *(const int2*)(rb[k] + (ch + 1) * 16);
                    ahi[k] = *(const int2*)(rb[k] + (ch + 1) * 16 + 8);
                }
            }

            // ---- B fragments + single product ----
            const uint32_t bo = (uint32_t)(s * BBUF + c2 * 32);
            unsigned Bh[8][2];
#pragma unroll
            for (int np = 0; np < 4; ++np)
                ldsm4(&Bh[2 * np][0], sBm + bo + np * (16 * BST));
#pragma unroll
            for (int n = 0; n < 8; ++n) mma_f16(acc[n], Ah, Bh[n][0], Bh[n][1]);
        }
    }

    // ---- denominators: quad-reduce per row ----
#pragma unroll
    for (int k = 0; k < 2; ++k) {
        den2[k] += __shfl_xor_sync(0xffffffffu, den2[k], 1);
        den2[k] += __shfl_xor_sync(0xffffffffu, den2[k], 2);
    }
    if ((l & 3) == 0) {
        g_pden[split][i0 + w * 16 + rq]     = den2[0];
        g_pden[split][i0 + w * 16 + 8 + rq] = den2[1];
    }

    // ---- write fp32 partial numerators ----
    {
        const int row = i0 + w * 16 + rq;
#pragma unroll
        for (int n = 0; n < 8; ++n) {
            *(float2*)&g_pacc[split][row][n * 8 + cq]     = make_float2(acc[n][0], acc[n][1]);
            *(float2*)&g_pacc[split][row + 8][n * 8 + cq] = make_float2(acc[n][2], acc[n][3]);
        }
    }
}

// ---------------------------------------------------------------------------
// Kernel 3: combine splits, normalize, ELU (float4-vectorized).
// ---------------------------------------------------------------------------
__global__ void __launch_bounds__(256) combine_kernel(float* __restrict__ out) {
    const int idx4 = blockIdx.x * 256 + threadIdx.x;   // over 8192*16
    const int i = idx4 >> 4;
    const int c4 = idx4 & 15;
    float4 acc = make_float4(0.f, 0.f, 0.f, 0.f);
    float den = 0.f;
#pragma unroll
    for (int sp = 0; sp < JSPLITS; ++sp) {
        float4 v = *(const float4*)&g_pacc[sp][i][c4 * 4];
        acc.x += v.x; acc.y += v.y; acc.z += v.z; acc.w += v.w;
        den += g_pden[sp][i];
    }
    if (den == 0.f) den = 1.f;
    float inv = 1.f / den;
    float4 o;
    o.x = acc.x * inv; o.x = o.x > 0.f ? o.x : expm1f(o.x);
    o.y = acc.y * inv; o.y = o.y > 0.f ? o.y : expm1f(o.y);
    o.z = acc.z * inv; o.z = o.z > 0.f ? o.z : expm1f(o.z);
    o.w = acc.w * inv; o.w = o.w > 0.f ? o.w : expm1f(o.w);
    *(float4*)&out[idx4 * 4] = o;
}

// ---------------------------------------------------------------------------
extern "C" void kernel_launch(void* const* d_in, const int* in_sizes, int n_in,
                              void* d_out, int out_size) {
    const float* h   = (const float*)d_in[0];
    const float* W   = (const float*)d_in[1];
    const float* a   = (const float*)d_in[2];
    const int*   adj = (const int*)d_in[3];
    float* out = (float*)d_out;

    prep_w<<<32, 256>>>(W);
    wh_mma<<<128, 128>>>(h, a);
    e2max_kernel<<<1, 256>>>();
    attn_kernel<<<(NN / 128) * JSPLITS, 256>>>(adj);
    combine_kernel<<<NN * 16 / 256, 256>>>(out);
}

// round 11
// speedup vs baseline: 1.1712x; 1.1712x over previous
#include <cuda_runtime.h>
#include <cuda_bf16.h>
#include <cuda_fp16.h>
#include <cstdint>

#define NN      8192
#define F_IN    512
#define NOUT    64
#define LRA     0.2f
#define JSPLITS 8
#define JLEN    (NN / JSPLITS)     // 1024
#define NCH     (JLEN / 16)        // 64 chunks of k=16
#define NBLK    (NCH / 2)          // 32 blocks of k=32
#define BST     80                 // padded bytes per n-row in staged B
#define BBUF    (64 * BST)         // 5120 B per stage

// ---------------- device scratch (no cudaMalloc allowed) -------------------
__device__ uint4 g_W_pk[64 * 32 * 4];                  // 128 KB (bf16 frags, wh GEMM)
__device__ __align__(16) __half g_WhT_hi[NOUT * NN];   // fp16 Wh^T, [n][j]
__device__ float g_e1[NN];
__device__ float g_e2[NN];
__device__ float g_m2;                                 // max_j e2[j]
__device__ float g_pacc[JSPLITS][NN][NOUT];
__device__ float g_pden[JSPLITS][NN];

// ---------------- helpers ---------------------------------------------------
__device__ __forceinline__ void mma_bf16(float* d, const unsigned* a,
                                         unsigned b0, unsigned b1) {
    asm volatile(
        "mma.sync.aligned.m16n8k16.row.col.f32.bf16.bf16.f32 "
        "{%0,%1,%2,%3}, {%4,%5,%6,%7}, {%8,%9}, {%0,%1,%2,%3};"
        : "+f"(d[0]), "+f"(d[1]), "+f"(d[2]), "+f"(d[3])
        : "r"(a[0]), "r"(a[1]), "r"(a[2]), "r"(a[3]), "r"(b0), "r"(b1));
}
__device__ __forceinline__ void mma_f16(float* d, const unsigned* a,
                                        unsigned b0, unsigned b1) {
    asm volatile(
        "mma.sync.aligned.m16n8k16.row.col.f32.f16.f16.f32 "
        "{%0,%1,%2,%3}, {%4,%5,%6,%7}, {%8,%9}, {%0,%1,%2,%3};"
        : "+f"(d[0]), "+f"(d[1]), "+f"(d[2]), "+f"(d[3])
        : "r"(a[0]), "r"(a[1]), "r"(a[2]), "r"(a[3]), "r"(b0), "r"(b1));
}
__device__ __forceinline__ void ldsm4(unsigned* r, uint32_t addr) {
    asm volatile("ldmatrix.sync.aligned.m8n8.x4.shared.b16 {%0,%1,%2,%3}, [%4];"
                 : "=r"(r[0]), "=r"(r[1]), "=r"(r[2]), "=r"(r[3]) : "r"(addr));
}
__device__ __forceinline__ unsigned cvt2b(float po, float pe) {  // bf16x2, lo=pe
    unsigned r;
    asm("cvt.rn.bf16x2.f32 %0, %1, %2;" : "=r"(r) : "f"(po), "f"(pe));
    return r;
}
__device__ __forceinline__ unsigned cvt2h(float po, float pe) {  // f16x2, lo=pe
    unsigned r;
    asm("cvt.rn.f16x2.f32 %0, %1, %2;" : "=r"(r) : "f"(po), "f"(pe));
    return r;
}
__device__ __forceinline__ float bfhf(float x) {
    return __bfloat162float(__float2bfloat16_rn(x));
}
__device__ __forceinline__ uint32_t smem_u32(const void* p) {
    return (uint32_t)__cvta_generic_to_shared(p);
}
__device__ __forceinline__ void cpa16(uint32_t dst, const void* src) {
    asm volatile("cp.async.cg.shared.global [%0], [%1], 16;" :: "r"(dst), "l"(src));
}
__device__ __forceinline__ void cpcommit() {
    asm volatile("cp.async.commit_group;" ::: "memory");
}
template <int N> __device__ __forceinline__ void cpwait() {
    asm volatile("cp.async.wait_group %0;" :: "n"(N) : "memory");
}

// ---------------------------------------------------------------------------
// Kernel 0: pack W (fp32 [512][64]) into bf16 hi/lo fragment layout (wh GEMM).
// ---------------------------------------------------------------------------
__global__ void __launch_bounds__(256) prep_w(const float* __restrict__ W) {
    const int t = blockIdx.x * 256 + threadIdx.x;
    const int s = t & 3, kc = (t >> 2) & 31, n = t >> 7;
    const int k0 = kc * 16 + 2 * s;
    float v00 = W[(k0 + 0) * 64 + n], v01 = W[(k0 + 1) * 64 + n];
    float v10 = W[(k0 + 8) * 64 + n], v11 = W[(k0 + 9) * 64 + n];
    float h00 = bfhf(v00), h01 = bfhf(v01), h10 = bfhf(v10), h11 = bfhf(v11);
    uint4 o;
    o.x = cvt2b(h01, h00);
    o.y = cvt2b(h11, h10);
    o.z = cvt2b(v01 - h01, v00 - h00);
    o.w = cvt2b(v11 - h11, v10 - h10);
    g_W_pk[(n * 32 + kc) * 4 + s] = o;
}

// ---------------------------------------------------------------------------
// Kernel 1: Wh = h @ W via mma.sync (3-product bf16 split; accurate e1/e2).
// Epilogue: e1/e2, WhT packed as fp16 row-major [n][j].
// ---------------------------------------------------------------------------
__global__ void __launch_bounds__(128, 1) wh_mma(const float* __restrict__ h,
                                                 const float* __restrict__ a) {
    __shared__ float s_h[3][64][20];
    __shared__ float s_t[64][65];

    const int tid = threadIdx.x;
    const int w = tid >> 5;
    const int l = tid & 31;
    const int r = l >> 2;
    const int c = (l & 3) * 2;
    const int node0 = blockIdx.x * 64;

    const uint32_t shb = smem_u32(&s_h[0][0][0]);
    auto stage = [&](int kc, int s) {
        const int row = tid >> 1, half = tid & 1;
        const float* src = h + (size_t)(node0 + row) * F_IN + kc * 16 + half * 8;
        uint32_t dst = shb + (uint32_t)((s * 64 + row) * 20 + half * 8) * 4;
        cpa16(dst, src);
        cpa16(dst + 16, src + 4);
    };

    stage(0, 0); cpcommit();
    stage(1, 1); cpcommit();

    float acc[8][4];
#pragma unroll
    for (int n = 0; n < 8; ++n)
#pragma unroll
        for (int q = 0; q < 4; ++q) acc[n][q] = 0.f;

    const uint4* __restrict__ wpk = g_W_pk;

    for (int kc = 0; kc < 32; ++kc) {
        const int ss = kc % 3;
        if (kc + 1 < 32) cpwait<1>(); else cpwait<0>();
        __syncthreads();
        if (kc + 2 < 32) { stage(kc + 2, (kc + 2) % 3); cpcommit(); }

        uint4 B4[8];
#pragma unroll
        for (int nt = 0; nt < 8; ++nt)
            B4[nt] = wpk[((nt * 8 + r) * 32 + kc) * 4 + (l & 3)];

        float2 v0 = *(const float2*)&s_h[ss][w * 16 + r][c];
        float2 v1 = *(const float2*)&s_h[ss][w * 16 + r + 8][c];
        float2 v2 = *(const float2*)&s_h[ss][w * 16 + r][c + 8];
        float2 v3 = *(const float2*)&s_h[ss][w * 16 + r + 8][c + 8];
        float h0x = bfhf(v0.x), h0y = bfhf(v0.y);
        float h1x = bfhf(v1.x), h1y = bfhf(v1.y);
        float h2x = bfhf(v2.x), h2y = bfhf(v2.y);
        float h3x = bfhf(v3.x), h3y = bfhf(v3.y);
        unsigned Ah[4], Al[4];
        Ah[0] = cvt2b(h0y, h0x); Al[0] = cvt2b(v0.y - h0y, v0.x - h0x);
        Ah[1] = cvt2b(h1y, h1x); Al[1] = cvt2b(v1.y - h1y, v1.x - h1x);
        Ah[2] = cvt2b(h2y, h2x); Al[2] = cvt2b(v2.y - h2y, v2.x - h2x);
        Ah[3] = cvt2b(h3y, h3x); Al[3] = cvt2b(v3.y - h3y, v3.x - h3x);

#pragma unroll
        for (int nt = 0; nt < 8; ++nt) mma_bf16(acc[nt], Ah, B4[nt].x, B4[nt].y);
#pragma unroll
        for (int nt = 0; nt < 8; ++nt) mma_bf16(acc[nt], Al, B4[nt].x, B4[nt].y);
#pragma unroll
        for (int nt = 0; nt < 8; ++nt) mma_bf16(acc[nt], Ah, B4[nt].z, B4[nt].w);
    }

    {
        float e1p0 = 0.f, e1p8 = 0.f, e2p0 = 0.f, e2p8 = 0.f;
#pragma unroll
        for (int nt = 0; nt < 8; ++nt) {
            float2 a1v = *(const float2*)&a[nt * 8 + c];
            float2 a2v = *(const float2*)&a[NOUT + nt * 8 + c];
            e1p0 += acc[nt][0] * a1v.x + acc[nt][1] * a1v.y;
            e1p8 += acc[nt][2] * a1v.x + acc[nt][3] * a1v.y;
            e2p0 += acc[nt][0] * a2v.x + acc[nt][1] * a2v.y;
            e2p8 += acc[nt][2] * a2v.x + acc[nt][3] * a2v.y;
        }
#pragma unroll
        for (int off = 1; off <= 2; off <<= 1) {
            e1p0 += __shfl_xor_sync(0xffffffffu, e1p0, off);
            e1p8 += __shfl_xor_sync(0xffffffffu, e1p8, off);
            e2p0 += __shfl_xor_sync(0xffffffffu, e2p0, off);
            e2p8 += __shfl_xor_sync(0xffffffffu, e2p8, off);
        }
        if ((l & 3) == 0) {
            g_e1[node0 + w * 16 + r]     = e1p0;
            g_e1[node0 + w * 16 + r + 8] = e1p8;
            g_e2[node0 + w * 16 + r]     = e2p0;
            g_e2[node0 + w * 16 + r + 8] = e2p8;
        }
    }

    __syncthreads();
#pragma unroll
    for (int nt = 0; nt < 8; ++nt) {
        s_t[w * 16 + r][nt * 8 + c]         = acc[nt][0];
        s_t[w * 16 + r][nt * 8 + c + 1]     = acc[nt][1];
        s_t[w * 16 + r + 8][nt * 8 + c]     = acc[nt][2];
        s_t[w * 16 + r + 8][nt * 8 + c + 1] = acc[nt][3];
    }
    __syncthreads();

    // pack WhT as fp16: thread -> (col n, half nh), 32 j's contiguous
    {
        const int col = tid >> 1, nh = tid & 1;
        float f[32];
#pragma unroll
        for (int j = 0; j < 32; ++j) f[j] = s_t[nh * 32 + j][col];
        unsigned hw[16];
#pragma unroll
        for (int q = 0; q < 16; ++q) hw[q] = cvt2h(f[2 * q + 1], f[2 * q]);
        const size_t base = (size_t)col * NN + blockIdx.x * 64 + nh * 32;
        uint4* dh = (uint4*)(g_WhT_hi + base);
#pragma unroll
        for (int q = 0; q < 4; ++q) dh[q] = *(uint4*)&hw[4 * q];
    }
}

// ---------------------------------------------------------------------------
// Kernel 1.5: global max of e2 (single CTA).
// ---------------------------------------------------------------------------
__global__ void __launch_bounds__(256) e2max_kernel() {
    __shared__ float sm[8];
    const int tid = threadIdx.x;
    float m = -1e30f;
    for (int k = tid; k < NN; k += 256) m = fmaxf(m, g_e2[k]);
#pragma unroll
    for (int off = 16; off; off >>= 1)
        m = fmaxf(m, __shfl_xor_sync(0xffffffffu, m, off));
    if ((tid & 31) == 0) sm[tid >> 5] = m;
    __syncthreads();
    if (tid == 0) {
        float mm = sm[0];
#pragma unroll
        for (int q = 1; q < 8; ++q) mm = fmaxf(mm, sm[q]);
        g_m2 = mm;
    }
}

// ---------------------------------------------------------------------------
// Kernel 2: fused masked-exp + single-product fp16 GEMM via mma.sync.
// p = exp(lrelu(e1+e2) - M_i) in (0,1] (fp16 A); Wh fp16 (B). 8 HMMA/chunk.
// occ = 2 CTAs/SM (R9-proven schedule); B via 3-stage cp.async + ldmatrix.
// ---------------------------------------------------------------------------
__global__ void __launch_bounds__(256, 2) attn_kernel(const int* __restrict__ adj) {
    __shared__ float s_e2[JLEN];                      // 4 KB
    __shared__ __align__(16) char s_B[3][BBUF];       // 15 KB

    const int tid = threadIdx.x;
    const int w = tid >> 5;
    const int l = tid & 31;
    const int i0 = (int)(blockIdx.x >> 3) * 128;
    const int split = blockIdx.x & 7;
    const int j0 = split * JLEN;

    {
        float4* d = (float4*)s_e2;
        const float4* s = (const float4*)(g_e2 + j0);
        for (int k = tid; k < JLEN / 4; k += 256) d[k] = s[k];
    }

    const int rq = l >> 2;          // 0..7
    const int cq = (l & 3) * 2;     // 0,2,4,6
    const float M2 = g_m2;

    float e1r[2], mi[2];
    const int* rb[2];
#pragma unroll
    for (int k = 0; k < 2; ++k) {
        int row = i0 + w * 16 + 8 * k + rq;
        e1r[k] = g_e1[row];
        float mv = e1r[k] + M2;
        mi[k] = mv > 0.f ? mv : LRA * mv;   // row max logit
        rb[k] = adj + (size_t)row * NN + j0 + cq;
    }

    const uint32_t sBs = smem_u32(&s_B[0][0]);
    // B tile for block blk: 64n x 32k fp16 = 4KB = one cpa16 per thread
    auto stage = [&](int blk, int s) {
        const int c = tid >> 6;              // 16B chunk 0..3 (8 halves)
        const int n = tid & 63;              // n-row
        const __half* src = g_WhT_hi + (size_t)n * NN + j0 + blk * 32 + c * 8;
        cpa16(sBs + (uint32_t)(s * BBUF + n * BST + c * 16), src);
    };

    const int g = l >> 3, lr = l & 7;
    const uint32_t sBm = sBs + (uint32_t)((lr + ((g >> 1) << 3)) * BST + ((g & 1) << 4));

    float acc[8][4];
#pragma unroll
    for (int n = 0; n < 8; ++n)
#pragma unroll
        for (int q = 0; q < 4; ++q) acc[n][q] = 0.f;
    float den2[2] = {0.f, 0.f};

    stage(0, 0); cpcommit();
    stage(1, 1); cpcommit();
    int2 alo[2], ahi[2];
#pragma unroll
    for (int k = 0; k < 2; ++k) {
        alo[k] = *(const int2*)(rb[k]);
        ahi[k] = *(const int2*)(rb[k] + 8);
    }

    for (int blk = 0; blk < NBLK; ++blk) {
        const int s = blk % 3;
        if (blk + 1 < NBLK) cpwait<1>(); else cpwait<0>();
        __syncthreads();
        if (blk + 2 < NBLK) { stage(blk + 2, (blk + 2) % 3); cpcommit(); }

#pragma unroll
        for (int c2 = 0; c2 < 2; ++c2) {
            const int ch = blk * 2 + c2;

            // ---- A fragments: shifted masked exp, fp16 ----
            const float* e2p = s_e2 + ch * 16;
            float2 e2a = *(const float2*)(e2p + cq);
            float2 e2b = *(const float2*)(e2p + cq + 8);
            unsigned Ah[4];
#pragma unroll
            for (int k = 0; k < 2; ++k) {
                const float e1v = e1r[k];
                float s0 = e1v + e2a.x; s0 = (s0 > 0.f ? s0 : LRA * s0) - mi[k];
                float s1 = e1v + e2a.y; s1 = (s1 > 0.f ? s1 : LRA * s1) - mi[k];
                float s2 = e1v + e2b.x; s2 = (s2 > 0.f ? s2 : LRA * s2) - mi[k];
                float s3 = e1v + e2b.y; s3 = (s3 > 0.f ? s3 : LRA * s3) - mi[k];
                float p0 = alo[k].x > 0 ? __expf(s0) : 0.f;
                float p1 = alo[k].y > 0 ? __expf(s1) : 0.f;
                float p2 = ahi[k].x > 0 ? __expf(s2) : 0.f;
                float p3 = ahi[k].y > 0 ? __expf(s3) : 0.f;
                den2[k] += (p0 + p1) + (p2 + p3);
                Ah[k]     = cvt2h(p1, p0);
                Ah[k + 2] = cvt2h(p3, p2);
            }

            // ---- prefetch next chunk's adj ----
            if (ch + 1 < NCH) {
#pragma unroll
                for (int k = 0; k < 2; ++k) {
                    alo[k] = *(const int2*)(rb[k] + (ch + 1) * 16);
                    ahi[k] = *(const int2*)(rb[k] + (ch + 1) * 16 + 8);
                }
            }

            // ---- B fragments + single product ----
            const uint32_t bo = (uint32_t)(s * BBUF + c2 * 32);
            unsigned Bh[8][2];
#pragma unroll
            for (int np = 0; np < 4; ++np)
                ldsm4(&Bh[2 * np][0], sBm + bo + np * (16 * BST));
#pragma unroll
            for (int n = 0; n < 8; ++n) mma_f16(acc[n], Ah, Bh[n][0], Bh[n][1]);
        }
    }

    // ---- denominators: quad-reduce per row ----
#pragma unroll
    for (int k = 0; k < 2; ++k) {
        den2[k] += __shfl_xor_sync(0xffffffffu, den2[k], 1);
        den2[k] += __shfl_xor_sync(0xffffffffu, den2[k], 2);
    }
    if ((l & 3) == 0) {
        g_pden[split][i0 + w * 16 + rq]     = den2[0];
        g_pden[split][i0 + w * 16 + 8 + rq] = den2[1];
    }

    // ---- write fp32 partial numerators ----
    {
        const int row = i0 + w * 16 + rq;
#pragma unroll
        for (int n = 0; n < 8; ++n) {
            *(float2*)&g_pacc[split][row][n * 8 + cq]     = make_float2(acc[n][0], acc[n][1]);
            *(float2*)&g_pacc[split][row + 8][n * 8 + cq] = make_float2(acc[n][2], acc[n][3]);
        }
    }
}

// ---------------------------------------------------------------------------
// Kernel 3: combine splits, normalize, ELU (float4-vectorized).
// ---------------------------------------------------------------------------
__global__ void __launch_bounds__(256) combine_kernel(float* __restrict__ out) {
    const int idx4 = blockIdx.x * 256 + threadIdx.x;   // over 8192*16
    const int i = idx4 >> 4;
    const int c4 = idx4 & 15;
    float4 acc = make_float4(0.f, 0.f, 0.f, 0.f);
    float den = 0.f;
#pragma unroll
    for (int sp = 0; sp < JSPLITS; ++sp) {
        float4 v = *(const float4*)&g_pacc[sp][i][c4 * 4];
        acc.x += v.x; acc.y += v.y; acc.z += v.z; acc.w += v.w;
        den += g_pden[sp][i];
    }
    if (den == 0.f) den = 1.f;
    float inv = 1.f / den;
    float4 o;
    o.x = acc.x * inv; o.x = o.x > 0.f ? o.x : expm1f(o.x);
    o.y = acc.y * inv; o.y = o.y > 0.f ? o.y : expm1f(o.y);
    o.z = acc.z * inv; o.z = o.z > 0.f ? o.z : expm1f(o.z);
    o.w = acc.w * inv; o.w = o.w > 0.f ? o.w : expm1f(o.w);
    *(float4*)&out[idx4 * 4] = o;
}

// ---------------------------------------------------------------------------
extern "C" void kernel_launch(void* const* d_in, const int* in_sizes, int n_in,
                              void* d_out, int out_size) {
    const float* h   = (const float*)d_in[0];
    const float* W   = (const float*)d_in[1];
    const float* a   = (const float*)d_in[2];
    const int*   adj = (const int*)d_in[3];
    float* out = (float*)d_out;

    prep_w<<<32, 256>>>(W);
    wh_mma<<<128, 128>>>(h, a);
    e2max_kernel<<<1, 256>>>();
    attn_kernel<<<(NN / 128) * JSPLITS, 256>>>(adj);
    combine_kernel<<<NN * 16 / 256, 256>>>(out);
}

// round 12
// speedup vs baseline: 1.4375x; 1.2274x over previous
#include <cuda_runtime.h>
#include <cuda_bf16.h>
#include <cuda_fp16.h>
#include <cstdint>

#define NN      8192
#define F_IN    512
#define NOUT    64
#define LRA     0.2f
#define L2E     1.4426950408889634f
#define JSPLITS 8
#define JLEN    (NN / JSPLITS)     // 1024
#define NCH     (JLEN / 16)        // 64 chunks of k=16
#define NBLK    (NCH / 2)          // 32 blocks of k=32
#define BST     80
#define BBUF    (64 * BST)

// ---------------- device scratch (no cudaMalloc allowed) -------------------
__device__ uint4 g_W_pk[64 * 32 * 4];
__device__ __align__(16) __half g_WhT_hi[NOUT * NN];
__device__ float g_e1[NN];
__device__ float g_e2[NN];
__device__ float g_m2;
__device__ float g_pacc[JSPLITS][NN][NOUT];
__device__ float g_pden[JSPLITS][NN];
__device__ int   g_cnt[64];

// ---------------- helpers ---------------------------------------------------
__device__ __forceinline__ void mma_bf16(float* d, const unsigned* a,
                                         unsigned b0, unsigned b1) {
    asm volatile(
        "mma.sync.aligned.m16n8k16.row.col.f32.bf16.bf16.f32 "
        "{%0,%1,%2,%3}, {%4,%5,%6,%7}, {%8,%9}, {%0,%1,%2,%3};"
        : "+f"(d[0]), "+f"(d[1]), "+f"(d[2]), "+f"(d[3])
        : "r"(a[0]), "r"(a[1]), "r"(a[2]), "r"(a[3]), "r"(b0), "r"(b1));
}
__device__ __forceinline__ void mma_f16(float* d, const unsigned* a,
                                        unsigned b0, unsigned b1) {
    asm volatile(
        "mma.sync.aligned.m16n8k16.row.col.f32.f16.f16.f32 "
        "{%0,%1,%2,%3}, {%4,%5,%6,%7}, {%8,%9}, {%0,%1,%2,%3};"
        : "+f"(d[0]), "+f"(d[1]), "+f"(d[2]), "+f"(d[3])
        : "r"(a[0]), "r"(a[1]), "r"(a[2]), "r"(a[3]), "r"(b0), "r"(b1));
}
__device__ __forceinline__ void ldsm4(unsigned* r, uint32_t addr) {
    asm volatile("ldmatrix.sync.aligned.m8n8.x4.shared.b16 {%0,%1,%2,%3}, [%4];"
                 : "=r"(r[0]), "=r"(r[1]), "=r"(r[2]), "=r"(r[3]) : "r"(addr));
}
__device__ __forceinline__ unsigned cvt2b(float po, float pe) {
    unsigned r;
    asm("cvt.rn.bf16x2.f32 %0, %1, %2;" : "=r"(r) : "f"(po), "f"(pe));
    return r;
}
__device__ __forceinline__ unsigned cvt2h(float po, float pe) {
    unsigned r;
    asm("cvt.rn.f16x2.f32 %0, %1, %2;" : "=r"(r) : "f"(po), "f"(pe));
    return r;
}
__device__ __forceinline__ float ex2a(float x) {
    float r;
    asm("ex2.approx.ftz.f32 %0, %1;" : "=f"(r) : "f"(x));
    return r;
}
__device__ __forceinline__ float bfhf(float x) {
    return __bfloat162float(__float2bfloat16_rn(x));
}
__device__ __forceinline__ uint32_t smem_u32(const void* p) {
    return (uint32_t)__cvta_generic_to_shared(p);
}
__device__ __forceinline__ void cpa16(uint32_t dst, const void* src) {
    asm volatile("cp.async.cg.shared.global [%0], [%1], 16;" :: "r"(dst), "l"(src));
}
__device__ __forceinline__ void cpcommit() {
    asm volatile("cp.async.commit_group;" ::: "memory");
}
template <int N> __device__ __forceinline__ void cpwait() {
    asm volatile("cp.async.wait_group %0;" :: "n"(N) : "memory");
}

// ---------------------------------------------------------------------------
// Kernel 0: pack W into bf16 hi/lo fragment layout.
// ---------------------------------------------------------------------------
__global__ void __launch_bounds__(256) prep_w(const float* __restrict__ W) {
    const int t = blockIdx.x * 256 + threadIdx.x;
    const int s = t & 3, kc = (t >> 2) & 31, n = t >> 7;
    const int k0 = kc * 16 + 2 * s;
    float v00 = W[(k0 + 0) * 64 + n], v01 = W[(k0 + 1) * 64 + n];
    float v10 = W[(k0 + 8) * 64 + n], v11 = W[(k0 + 9) * 64 + n];
    float h00 = bfhf(v00), h01 = bfhf(v01), h10 = bfhf(v10), h11 = bfhf(v11);
    uint4 o;
    o.x = cvt2b(h01, h00);
    o.y = cvt2b(h11, h10);
    o.z = cvt2b(v01 - h01, v00 - h00);
    o.w = cvt2b(v11 - h11, v10 - h10);
    g_W_pk[(n * 32 + kc) * 4 + s] = o;
}

// ---------------------------------------------------------------------------
// Kernel 1: Wh = h @ W via mma.sync (3-product bf16 split).
// 256 thr / 8 warps: warp (wg, half) = rows wg*16.. x cols half*32..
// (2 warps/SMSP, 12-HMMA chains). Epilogue: e1/e2 (cross-warp smem combine),
// fp16 WhT pack.
// ---------------------------------------------------------------------------
__global__ void __launch_bounds__(256, 1) wh_mma(const float* __restrict__ h,
                                                 const float* __restrict__ a) {
    __shared__ float s_h[3][64][20];
    __shared__ float s_t[64][65];
    __shared__ float s_e1p[8][16];
    __shared__ float s_e2p[8][16];

    const int tid = threadIdx.x;
    const int w = tid >> 5;
    const int l = tid & 31;
    const int wg = w >> 1;          // row group 0..3
    const int half = w & 1;         // n half 0..1
    const int r = l >> 2;
    const int c = (l & 3) * 2;
    const int node0 = blockIdx.x * 64;

    const uint32_t shb = smem_u32(&s_h[0][0][0]);
    auto stage = [&](int kc, int s) {
        const int row = tid >> 2, q4 = tid & 3;
        const float* src = h + (size_t)(node0 + row) * F_IN + kc * 16 + q4 * 4;
        cpa16(shb + (uint32_t)((s * 64 + row) * 20 + q4 * 4) * 4, src);
    };

    stage(0, 0); cpcommit();
    stage(1, 1); cpcommit();

    float acc[4][4];
#pragma unroll
    for (int n = 0; n < 4; ++n)
#pragma unroll
        for (int q = 0; q < 4; ++q) acc[n][q] = 0.f;

    const uint4* __restrict__ wpk = g_W_pk;

    for (int kc = 0; kc < 32; ++kc) {
        const int ss = kc % 3;
        if (kc + 1 < 32) cpwait<1>(); else cpwait<0>();
        __syncthreads();
        if (kc + 2 < 32) { stage(kc + 2, (kc + 2) % 3); cpcommit(); }

        uint4 B4[4];
#pragma unroll
        for (int nt = 0; nt < 4; ++nt)
            B4[nt] = wpk[(((half * 4 + nt) * 8 + r) * 32 + kc) * 4 + (l & 3)];

        float2 v0 = *(const float2*)&s_h[ss][wg * 16 + r][c];
        float2 v1 = *(const float2*)&s_h[ss][wg * 16 + r + 8][c];
        float2 v2 = *(const float2*)&s_h[ss][wg * 16 + r][c + 8];
        float2 v3 = *(const float2*)&s_h[ss][wg * 16 + r + 8][c + 8];
        float h0x = bfhf(v0.x), h0y = bfhf(v0.y);
        float h1x = bfhf(v1.x), h1y = bfhf(v1.y);
        float h2x = bfhf(v2.x), h2y = bfhf(v2.y);
        float h3x = bfhf(v3.x), h3y = bfhf(v3.y);
        unsigned Ah[4], Al[4];
        Ah[0] = cvt2b(h0y, h0x); Al[0] = cvt2b(v0.y - h0y, v0.x - h0x);
        Ah[1] = cvt2b(h1y, h1x); Al[1] = cvt2b(v1.y - h1y, v1.x - h1x);
        Ah[2] = cvt2b(h2y, h2x); Al[2] = cvt2b(v2.y - h2y, v2.x - h2x);
        Ah[3] = cvt2b(h3y, h3x); Al[3] = cvt2b(v3.y - h3y, v3.x - h3x);

#pragma unroll
        for (int nt = 0; nt < 4; ++nt) mma_bf16(acc[nt], Ah, B4[nt].x, B4[nt].y);
#pragma unroll
        for (int nt = 0; nt < 4; ++nt) mma_bf16(acc[nt], Al, B4[nt].x, B4[nt].y);
#pragma unroll
        for (int nt = 0; nt < 4; ++nt) mma_bf16(acc[nt], Ah, B4[nt].z, B4[nt].w);
    }

    // ---- e1/e2 partials over this warp's 32 cols ----
    {
        float e1p0 = 0.f, e1p8 = 0.f, e2p0 = 0.f, e2p8 = 0.f;
#pragma unroll
        for (int nt = 0; nt < 4; ++nt) {
            const int col = half * 32 + nt * 8 + c;
            float2 a1v = *(const float2*)&a[col];
            float2 a2v = *(const float2*)&a[NOUT + col];
            e1p0 += acc[nt][0] * a1v.x + acc[nt][1] * a1v.y;
            e1p8 += acc[nt][2] * a1v.x + acc[nt][3] * a1v.y;
            e2p0 += acc[nt][0] * a2v.x + acc[nt][1] * a2v.y;
            e2p8 += acc[nt][2] * a2v.x + acc[nt][3] * a2v.y;
        }
#pragma unroll
        for (int off = 1; off <= 2; off <<= 1) {
            e1p0 += __shfl_xor_sync(0xffffffffu, e1p0, off);
            e1p8 += __shfl_xor_sync(0xffffffffu, e1p8, off);
            e2p0 += __shfl_xor_sync(0xffffffffu, e2p0, off);
            e2p8 += __shfl_xor_sync(0xffffffffu, e2p8, off);
        }
        if ((l & 3) == 0) {
            s_e1p[w][r] = e1p0; s_e1p[w][r + 8] = e1p8;
            s_e2p[w][r] = e2p0; s_e2p[w][r + 8] = e2p8;
        }
    }

    // ---- transpose acc into s_t ----
#pragma unroll
    for (int nt = 0; nt < 4; ++nt) {
        const int cb = half * 32 + nt * 8 + c;
        s_t[wg * 16 + r][cb]         = acc[nt][0];
        s_t[wg * 16 + r][cb + 1]     = acc[nt][1];
        s_t[wg * 16 + r + 8][cb]     = acc[nt][2];
        s_t[wg * 16 + r + 8][cb + 1] = acc[nt][3];
    }
    __syncthreads();

    if (tid < 64) {
        const int wg2 = tid >> 4, rr = tid & 15;
        g_e1[node0 + wg2 * 16 + rr] = s_e1p[2 * wg2][rr] + s_e1p[2 * wg2 + 1][rr];
        g_e2[node0 + wg2 * 16 + rr] = s_e2p[2 * wg2][rr] + s_e2p[2 * wg2 + 1][rr];
    }

    // ---- pack WhT fp16: thread -> (col, j-quarter of 16) ----
    {
        const int col = tid >> 2, nh = tid & 3;
        float f[16];
#pragma unroll
        for (int j = 0; j < 16; ++j) f[j] = s_t[nh * 16 + j][col];
        unsigned hw[8];
#pragma unroll
        for (int q = 0; q < 8; ++q) hw[q] = cvt2h(f[2 * q + 1], f[2 * q]);
        uint4* dh = (uint4*)(g_WhT_hi + (size_t)col * NN + blockIdx.x * 64 + nh * 16);
        dh[0] = *(uint4*)&hw[0];
        dh[1] = *(uint4*)&hw[4];
    }
}

// ---------------------------------------------------------------------------
// Kernel 1.5: global max of e2 (single CTA) + reset combine counters.
// ---------------------------------------------------------------------------
__global__ void __launch_bounds__(256) e2max_kernel() {
    __shared__ float sm[8];
    const int tid = threadIdx.x;
    if (tid < 64) g_cnt[tid] = 0;
    float m = -1e30f;
    for (int k = tid; k < NN; k += 256) m = fmaxf(m, g_e2[k]);
#pragma unroll
    for (int off = 16; off; off >>= 1)
        m = fmaxf(m, __shfl_xor_sync(0xffffffffu, m, off));
    if ((tid & 31) == 0) sm[tid >> 5] = m;
    __syncthreads();
    if (tid == 0) {
        float mm = sm[0];
#pragma unroll
        for (int q = 1; q < 8; ++q) mm = fmaxf(mm, sm[q]);
        g_m2 = mm;
    }
}

// ---------------------------------------------------------------------------
// Kernel 2: fused masked-exp + fp16 GEMM + fused combine.
// - base-2 domain (prescaled by log2e): p = ex2(lrelu2(e1'+e2') - mi')
// - denominator via ones-B HMMA (tensor pipe, no scalar FADDs/shfl)
// - last CTA per row-tile performs the combine+ELU (atomic counter).
// ---------------------------------------------------------------------------
__global__ void __launch_bounds__(256, 2) attn_kernel(const int* __restrict__ adj,
                                                      float* __restrict__ out) {
    __shared__ float s_e2[JLEN];
    __shared__ __align__(16) char s_B[3][BBUF];
    __shared__ int s_last;

    const int tid = threadIdx.x;
    const int w = tid >> 5;
    const int l = tid & 31;
    const int i0 = (int)(blockIdx.x >> 3) * 128;
    const int split = blockIdx.x & 7;
    const int j0 = split * JLEN;

    {
        float4* d = (float4*)s_e2;
        const float4* s = (const float4*)(g_e2 + j0);
        for (int k = tid; k < JLEN / 4; k += 256) {
            float4 v = s[k];
            v.x *= L2E; v.y *= L2E; v.z *= L2E; v.w *= L2E;
            d[k] = v;
        }
    }

    const int rq = l >> 2;
    const int cq = (l & 3) * 2;
    const float M2s = g_m2 * L2E;

    float e1r[2], mi[2];
    const int* rb[2];
#pragma unroll
    for (int k = 0; k < 2; ++k) {
        int row = i0 + w * 16 + 8 * k + rq;
        e1r[k] = g_e1[row] * L2E;
        float mv = e1r[k] + M2s;
        mi[k] = mv > 0.f ? mv : LRA * mv;
        rb[k] = adj + (size_t)row * NN + j0 + cq;
    }

    const uint32_t sBs = smem_u32(&s_B[0][0]);
    auto stage = [&](int blk, int s) {
        const int c = tid >> 6;
        const int n = tid & 63;
        const __half* src = g_WhT_hi + (size_t)n * NN + j0 + blk * 32 + c * 8;
        cpa16(sBs + (uint32_t)(s * BBUF + n * BST + c * 16), src);
    };

    const int g = l >> 3, lr = l & 7;
    const uint32_t sBm = sBs + (uint32_t)((lr + ((g >> 1) << 3)) * BST + ((g & 1) << 4));

    float acc[8][4];
#pragma unroll
    for (int n = 0; n < 8; ++n)
#pragma unroll
        for (int q = 0; q < 4; ++q) acc[n][q] = 0.f;
    float accd[4] = {0.f, 0.f, 0.f, 0.f};     // ones-GEMM denominator
    const unsigned ONES = 0x3C003C00u;        // half2(1.0, 1.0)

    stage(0, 0); cpcommit();
    stage(1, 1); cpcommit();
    int2 alo[2], ahi[2];
#pragma unroll
    for (int k = 0; k < 2; ++k) {
        alo[k] = *(const int2*)(rb[k]);
        ahi[k] = *(const int2*)(rb[k] + 8);
    }

    for (int blk = 0; blk < NBLK; ++blk) {
        const int s = blk % 3;
        if (blk + 1 < NBLK) cpwait<1>(); else cpwait<0>();
        __syncthreads();
        if (blk + 2 < NBLK) { stage(blk + 2, (blk + 2) % 3); cpcommit(); }

#pragma unroll
        for (int c2 = 0; c2 < 2; ++c2) {
            const int ch = blk * 2 + c2;

            // ---- A fragments: shifted masked exp (base-2), fp16 ----
            const float* e2p = s_e2 + ch * 16;
            float2 e2a = *(const float2*)(e2p + cq);
            float2 e2b = *(const float2*)(e2p + cq + 8);
            unsigned Ah[4];
#pragma unroll
            for (int k = 0; k < 2; ++k) {
                const float e1v = e1r[k];
                float s0 = e1v + e2a.x; s0 = (s0 > 0.f ? s0 : LRA * s0) - mi[k];
                float s1 = e1v + e2a.y; s1 = (s1 > 0.f ? s1 : LRA * s1) - mi[k];
                float s2 = e1v + e2b.x; s2 = (s2 > 0.f ? s2 : LRA * s2) - mi[k];
                float s3 = e1v + e2b.y; s3 = (s3 > 0.f ? s3 : LRA * s3) - mi[k];
                float p0 = alo[k].x > 0 ? ex2a(s0) : 0.f;
                float p1 = alo[k].y > 0 ? ex2a(s1) : 0.f;
                float p2 = ahi[k].x > 0 ? ex2a(s2) : 0.f;
                float p3 = ahi[k].y > 0 ? ex2a(s3) : 0.f;
                Ah[k]     = cvt2h(p1, p0);
                Ah[k + 2] = cvt2h(p3, p2);
            }

            if (ch + 1 < NCH) {
#pragma unroll
                for (int k = 0; k < 2; ++k) {
                    alo[k] = *(const int2*)(rb[k] + (ch + 1) * 16);
                    ahi[k] = *(const int2*)(rb[k] + (ch + 1) * 16 + 8);
                }
            }

            // ---- B fragments + products (+ ones-GEMM for denominator) ----
            const uint32_t bo = (uint32_t)(s * BBUF + c2 * 32);
            unsigned Bh[8][2];
#pragma unroll
            for (int np = 0; np < 4; ++np)
                ldsm4(&Bh[2 * np][0], sBm + bo + np * (16 * BST));
#pragma unroll
            for (int n = 0; n < 8; ++n) mma_f16(acc[n], Ah, Bh[n][0], Bh[n][1]);
            mma_f16(accd, Ah, ONES, ONES);
        }
    }

    // ---- write partials (den = accd: identical across cols of ones-tile) ----
    if ((l & 3) == 0) {
        g_pden[split][i0 + w * 16 + rq]     = accd[0];
        g_pden[split][i0 + w * 16 + 8 + rq] = accd[2];
    }
    {
        const int row = i0 + w * 16 + rq;
#pragma unroll
        for (int n = 0; n < 8; ++n) {
            *(float2*)&g_pacc[split][row][n * 8 + cq]     = make_float2(acc[n][0], acc[n][1]);
            *(float2*)&g_pacc[split][row + 8][n * 8 + cq] = make_float2(acc[n][2], acc[n][3]);
        }
    }

    // ---- fused combine: last CTA of this row-tile reduces all splits ----
    __threadfence();
    __syncthreads();
    if (tid == 0)
        s_last = (atomicAdd(&g_cnt[blockIdx.x >> 3], 1) == JSPLITS - 1);
    __syncthreads();
    if (s_last) {
        __threadfence();
        for (int t = tid; t < 128 * 16; t += 256) {
            const int row = i0 + (t >> 4);
            const int c4 = (t & 15) * 4;
            float4 av = make_float4(0.f, 0.f, 0.f, 0.f);
            float den = 0.f;
#pragma unroll
            for (int sp = 0; sp < JSPLITS; ++sp) {
                float4 v = *(const float4*)&g_pacc[sp][row][c4];
                av.x += v.x; av.y += v.y; av.z += v.z; av.w += v.w;
                den += g_pden[sp][row];
            }
            if (den == 0.f) den = 1.f;
            float inv = 1.f / den;
            float4 o;
            o.x = av.x * inv; o.x = o.x > 0.f ? o.x : expm1f(o.x);
            o.y = av.y * inv; o.y = o.y > 0.f ? o.y : expm1f(o.y);
            o.z = av.z * inv; o.z = o.z > 0.f ? o.z : expm1f(o.z);
            o.w = av.w * inv; o.w = o.w > 0.f ? o.w : expm1f(o.w);
            *(float4*)&out[(size_t)row * NOUT + c4] = o;
        }
    }
}

// ---------------------------------------------------------------------------
extern "C" void kernel_launch(void* const* d_in, const int* in_sizes, int n_in,
                              void* d_out, int out_size) {
    const float* h   = (const float*)d_in[0];
    const float* W   = (const float*)d_in[1];
    const float* a   = (const float*)d_in[2];
    const int*   adj = (const int*)d_in[3];
    float* out = (float*)d_out;

    prep_w<<<32, 256>>>(W);
    wh_mma<<<128, 256>>>(h, a);
    e2max_kernel<<<1, 256>>>();
    attn_kernel<<<(NN / 128) * JSPLITS, 256>>>(adj, out);
}

// round 13
// speedup vs baseline: 1.5587x; 1.0843x over previous
#include <cuda_runtime.h>
#include <cuda_bf16.h>
#include <cuda_fp16.h>
#include <cstdint>

#define NN      8192
#define F_IN    512
#define NOUT    64
#define LRA     0.2f
#define L2E     1.4426950408889634f
#define JSPLITS 8
#define JLEN    (NN / JSPLITS)     // 1024
#define NCH     (JLEN / 16)        // 64 chunks of k=16
#define NBLK    (NCH / 2)          // 32 blocks of k=32
#define BST     80
#define BBUF    (64 * BST)

// ---------------- device scratch (no cudaMalloc allowed) -------------------
__device__ uint4 g_W_pk[64 * 32 * 4];
__device__ __align__(16) __half g_WhT_hi[NOUT * NN];
__device__ float g_e1[NN];
__device__ float g_e2[NN];
__device__ float g_m2;
__device__ float g_pacc[JSPLITS][NN][NOUT];
__device__ float g_pden[JSPLITS][NN];
__device__ int   g_cnt[64];

// ---------------- helpers ---------------------------------------------------
__device__ __forceinline__ void mma_bf16(float* d, const unsigned* a,
                                         unsigned b0, unsigned b1) {
    asm volatile(
        "mma.sync.aligned.m16n8k16.row.col.f32.bf16.bf16.f32 "
        "{%0,%1,%2,%3}, {%4,%5,%6,%7}, {%8,%9}, {%0,%1,%2,%3};"
        : "+f"(d[0]), "+f"(d[1]), "+f"(d[2]), "+f"(d[3])
        : "r"(a[0]), "r"(a[1]), "r"(a[2]), "r"(a[3]), "r"(b0), "r"(b1));
}
__device__ __forceinline__ void mma_f16(float* d, const unsigned* a,
                                        unsigned b0, unsigned b1) {
    asm volatile(
        "mma.sync.aligned.m16n8k16.row.col.f32.f16.f16.f32 "
        "{%0,%1,%2,%3}, {%4,%5,%6,%7}, {%8,%9}, {%0,%1,%2,%3};"
        : "+f"(d[0]), "+f"(d[1]), "+f"(d[2]), "+f"(d[3])
        : "r"(a[0]), "r"(a[1]), "r"(a[2]), "r"(a[3]), "r"(b0), "r"(b1));
}
__device__ __forceinline__ void ldsm4(unsigned* r, uint32_t addr) {
    asm volatile("ldmatrix.sync.aligned.m8n8.x4.shared.b16 {%0,%1,%2,%3}, [%4];"
                 : "=r"(r[0]), "=r"(r[1]), "=r"(r[2]), "=r"(r[3]) : "r"(addr));
}
__device__ __forceinline__ unsigned cvt2b(float po, float pe) {
    unsigned r;
    asm("cvt.rn.bf16x2.f32 %0, %1, %2;" : "=r"(r) : "f"(po), "f"(pe));
    return r;
}
__device__ __forceinline__ unsigned cvt2h(float po, float pe) {
    unsigned r;
    asm("cvt.rn.f16x2.f32 %0, %1, %2;" : "=r"(r) : "f"(po), "f"(pe));
    return r;
}
__device__ __forceinline__ float ex2a(float x) {
    float r;
    asm("ex2.approx.ftz.f32 %0, %1;" : "=f"(r) : "f"(x));
    return r;
}
__device__ __forceinline__ float bfhf(float x) {
    return __bfloat162float(__float2bfloat16_rn(x));
}
__device__ __forceinline__ uint32_t smem_u32(const void* p) {
    return (uint32_t)__cvta_generic_to_shared(p);
}
__device__ __forceinline__ void cpa16(uint32_t dst, const void* src) {
    asm volatile("cp.async.cg.shared.global [%0], [%1], 16;" :: "r"(dst), "l"(src));
}
__device__ __forceinline__ void cpcommit() {
    asm volatile("cp.async.commit_group;" ::: "memory");
}
template <int N> __device__ __forceinline__ void cpwait() {
    asm volatile("cp.async.wait_group %0;" :: "n"(N) : "memory");
}

// ---------------------------------------------------------------------------
// Kernel 0: pack W into bf16 hi/lo fragment layout.
// ---------------------------------------------------------------------------
__global__ void __launch_bounds__(256) prep_w(const float* __restrict__ W) {
    const int t = blockIdx.x * 256 + threadIdx.x;
    const int s = t & 3, kc = (t >> 2) & 31, n = t >> 7;
    const int k0 = kc * 16 + 2 * s;
    float v00 = W[(k0 + 0) * 64 + n], v01 = W[(k0 + 1) * 64 + n];
    float v10 = W[(k0 + 8) * 64 + n], v11 = W[(k0 + 9) * 64 + n];
    float h00 = bfhf(v00), h01 = bfhf(v01), h10 = bfhf(v10), h11 = bfhf(v11);
    uint4 o;
    o.x = cvt2b(h01, h00);
    o.y = cvt2b(h11, h10);
    o.z = cvt2b(v01 - h01, v00 - h00);
    o.w = cvt2b(v11 - h11, v10 - h10);
    g_W_pk[(n * 32 + kc) * 4 + s] = o;
}

// ---------------------------------------------------------------------------
// Kernel 1: Wh = h @ W via mma.sync (3-product bf16 split). (R12 structure)
// ---------------------------------------------------------------------------
__global__ void __launch_bounds__(256, 1) wh_mma(const float* __restrict__ h,
                                                 const float* __restrict__ a) {
    __shared__ float s_h[3][64][20];
    __shared__ float s_t[64][65];
    __shared__ float s_e1p[8][16];
    __shared__ float s_e2p[8][16];

    const int tid = threadIdx.x;
    const int w = tid >> 5;
    const int l = tid & 31;
    const int wg = w >> 1;
    const int half = w & 1;
    const int r = l >> 2;
    const int c = (l & 3) * 2;
    const int node0 = blockIdx.x * 64;

    const uint32_t shb = smem_u32(&s_h[0][0][0]);
    auto stage = [&](int kc, int s) {
        const int row = tid >> 2, q4 = tid & 3;
        const float* src = h + (size_t)(node0 + row) * F_IN + kc * 16 + q4 * 4;
        cpa16(shb + (uint32_t)((s * 64 + row) * 20 + q4 * 4) * 4, src);
    };

    stage(0, 0); cpcommit();
    stage(1, 1); cpcommit();

    float acc[4][4];
#pragma unroll
    for (int n = 0; n < 4; ++n)
#pragma unroll
        for (int q = 0; q < 4; ++q) acc[n][q] = 0.f;

    const uint4* __restrict__ wpk = g_W_pk;

    for (int kc = 0; kc < 32; ++kc) {
        const int ss = kc % 3;
        if (kc + 1 < 32) cpwait<1>(); else cpwait<0>();
        __syncthreads();
        if (kc + 2 < 32) { stage(kc + 2, (kc + 2) % 3); cpcommit(); }

        uint4 B4[4];
#pragma unroll
        for (int nt = 0; nt < 4; ++nt)
            B4[nt] = wpk[(((half * 4 + nt) * 8 + r) * 32 + kc) * 4 + (l & 3)];

        float2 v0 = *(const float2*)&s_h[ss][wg * 16 + r][c];
        float2 v1 = *(const float2*)&s_h[ss][wg * 16 + r + 8][c];
        float2 v2 = *(const float2*)&s_h[ss][wg * 16 + r][c + 8];
        float2 v3 = *(const float2*)&s_h[ss][wg * 16 + r + 8][c + 8];
        float h0x = bfhf(v0.x), h0y = bfhf(v0.y);
        float h1x = bfhf(v1.x), h1y = bfhf(v1.y);
        float h2x = bfhf(v2.x), h2y = bfhf(v2.y);
        float h3x = bfhf(v3.x), h3y = bfhf(v3.y);
        unsigned Ah[4], Al[4];
        Ah[0] = cvt2b(h0y, h0x); Al[0] = cvt2b(v0.y - h0y, v0.x - h0x);
        Ah[1] = cvt2b(h1y, h1x); Al[1] = cvt2b(v1.y - h1y, v1.x - h1x);
        Ah[2] = cvt2b(h2y, h2x); Al[2] = cvt2b(v2.y - h2y, v2.x - h2x);
        Ah[3] = cvt2b(h3y, h3x); Al[3] = cvt2b(v3.y - h3y, v3.x - h3x);

#pragma unroll
        for (int nt = 0; nt < 4; ++nt) mma_bf16(acc[nt], Ah, B4[nt].x, B4[nt].y);
#pragma unroll
        for (int nt = 0; nt < 4; ++nt) mma_bf16(acc[nt], Al, B4[nt].x, B4[nt].y);
#pragma unroll
        for (int nt = 0; nt < 4; ++nt) mma_bf16(acc[nt], Ah, B4[nt].z, B4[nt].w);
    }

    {
        float e1p0 = 0.f, e1p8 = 0.f, e2p0 = 0.f, e2p8 = 0.f;
#pragma unroll
        for (int nt = 0; nt < 4; ++nt) {
            const int col = half * 32 + nt * 8 + c;
            float2 a1v = *(const float2*)&a[col];
            float2 a2v = *(const float2*)&a[NOUT + col];
            e1p0 += acc[nt][0] * a1v.x + acc[nt][1] * a1v.y;
            e1p8 += acc[nt][2] * a1v.x + acc[nt][3] * a1v.y;
            e2p0 += acc[nt][0] * a2v.x + acc[nt][1] * a2v.y;
            e2p8 += acc[nt][2] * a2v.x + acc[nt][3] * a2v.y;
        }
#pragma unroll
        for (int off = 1; off <= 2; off <<= 1) {
            e1p0 += __shfl_xor_sync(0xffffffffu, e1p0, off);
            e1p8 += __shfl_xor_sync(0xffffffffu, e1p8, off);
            e2p0 += __shfl_xor_sync(0xffffffffu, e2p0, off);
            e2p8 += __shfl_xor_sync(0xffffffffu, e2p8, off);
        }
        if ((l & 3) == 0) {
            s_e1p[w][r] = e1p0; s_e1p[w][r + 8] = e1p8;
            s_e2p[w][r] = e2p0; s_e2p[w][r + 8] = e2p8;
        }
    }

#pragma unroll
    for (int nt = 0; nt < 4; ++nt) {
        const int cb = half * 32 + nt * 8 + c;
        s_t[wg * 16 + r][cb]         = acc[nt][0];
        s_t[wg * 16 + r][cb + 1]     = acc[nt][1];
        s_t[wg * 16 + r + 8][cb]     = acc[nt][2];
        s_t[wg * 16 + r + 8][cb + 1] = acc[nt][3];
    }
    __syncthreads();

    if (tid < 64) {
        const int wg2 = tid >> 4, rr = tid & 15;
        g_e1[node0 + wg2 * 16 + rr] = s_e1p[2 * wg2][rr] + s_e1p[2 * wg2 + 1][rr];
        g_e2[node0 + wg2 * 16 + rr] = s_e2p[2 * wg2][rr] + s_e2p[2 * wg2 + 1][rr];
    }

    {
        const int col = tid >> 2, nh = tid & 3;
        float f[16];
#pragma unroll
        for (int j = 0; j < 16; ++j) f[j] = s_t[nh * 16 + j][col];
        unsigned hw[8];
#pragma unroll
        for (int q = 0; q < 8; ++q) hw[q] = cvt2h(f[2 * q + 1], f[2 * q]);
        uint4* dh = (uint4*)(g_WhT_hi + (size_t)col * NN + blockIdx.x * 64 + nh * 16);
        dh[0] = *(uint4*)&hw[0];
        dh[1] = *(uint4*)&hw[4];
    }
}

// ---------------------------------------------------------------------------
// Kernel 1.5: global max of e2 (single CTA) + reset combine counters.
// ---------------------------------------------------------------------------
__global__ void __launch_bounds__(256) e2max_kernel() {
    __shared__ float sm[8];
    const int tid = threadIdx.x;
    if (tid < 64) g_cnt[tid] = 0;
    float m = -1e30f;
    for (int k = tid; k < NN; k += 256) m = fmaxf(m, g_e2[k]);
#pragma unroll
    for (int off = 16; off; off >>= 1)
        m = fmaxf(m, __shfl_xor_sync(0xffffffffu, m, off));
    if ((tid & 31) == 0) sm[tid >> 5] = m;
    __syncthreads();
    if (tid == 0) {
        float mm = sm[0];
#pragma unroll
        for (int q = 1; q < 8; ++q) mm = fmaxf(mm, sm[q]);
        g_m2 = mm;
    }
}

// ---------------------------------------------------------------------------
// Kernel 2: fused masked-exp + fp16 GEMM + ones-GEMM den + fused combine.
// NEW: adj register pipeline DEPTH-2 — load(ch+2) issued right after
// consuming buffer (ch&1); ~2 chunk-times of latency cover for DRAM.
// ---------------------------------------------------------------------------
__global__ void __launch_bounds__(256, 2) attn_kernel(const int* __restrict__ adj,
                                                      float* __restrict__ out) {
    __shared__ float s_e2[JLEN];
    __shared__ __align__(16) char s_B[3][BBUF];
    __shared__ int s_last;

    const int tid = threadIdx.x;
    const int w = tid >> 5;
    const int l = tid & 31;
    const int i0 = (int)(blockIdx.x >> 3) * 128;
    const int split = blockIdx.x & 7;
    const int j0 = split * JLEN;

    {
        float4* d = (float4*)s_e2;
        const float4* s = (const float4*)(g_e2 + j0);
        for (int k = tid; k < JLEN / 4; k += 256) {
            float4 v = s[k];
            v.x *= L2E; v.y *= L2E; v.z *= L2E; v.w *= L2E;
            d[k] = v;
        }
    }

    const int rq = l >> 2;
    const int cq = (l & 3) * 2;
    const float M2s = g_m2 * L2E;

    float e1r[2], mi[2];
    const int* rb[2];
#pragma unroll
    for (int k = 0; k < 2; ++k) {
        int row = i0 + w * 16 + 8 * k + rq;
        e1r[k] = g_e1[row] * L2E;
        float mv = e1r[k] + M2s;
        mi[k] = mv > 0.f ? mv : LRA * mv;
        rb[k] = adj + (size_t)row * NN + j0 + cq;
    }

    const uint32_t sBs = smem_u32(&s_B[0][0]);
    auto stage = [&](int blk, int s) {
        const int c = tid >> 6;
        const int n = tid & 63;
        const __half* src = g_WhT_hi + (size_t)n * NN + j0 + blk * 32 + c * 8;
        cpa16(sBs + (uint32_t)(s * BBUF + n * BST + c * 16), src);
    };

    const int g = l >> 3, lr = l & 7;
    const uint32_t sBm = sBs + (uint32_t)((lr + ((g >> 1) << 3)) * BST + ((g & 1) << 4));

    float acc[8][4];
#pragma unroll
    for (int n = 0; n < 8; ++n)
#pragma unroll
        for (int q = 0; q < 4; ++q) acc[n][q] = 0.f;
    float accd[4] = {0.f, 0.f, 0.f, 0.f};
    const unsigned ONES = 0x3C003C00u;

    // depth-2 adj register pipeline: buf b holds chunk data for ch with ch&1==b
    int2 alo[2][2], ahi[2][2];
    auto loadAdj = [&](int ch) {
        const int b = ch & 1;
#pragma unroll
        for (int k = 0; k < 2; ++k) {
            alo[b][k] = *(const int2*)(rb[k] + ch * 16);
            ahi[b][k] = *(const int2*)(rb[k] + ch * 16 + 8);
        }
    };

    stage(0, 0); cpcommit();
    stage(1, 1); cpcommit();
    loadAdj(0);
    loadAdj(1);

    for (int blk = 0; blk < NBLK; ++blk) {
        const int s = blk % 3;
        if (blk + 1 < NBLK) cpwait<1>(); else cpwait<0>();
        __syncthreads();
        if (blk + 2 < NBLK) { stage(blk + 2, (blk + 2) % 3); cpcommit(); }

#pragma unroll
        for (int c2 = 0; c2 < 2; ++c2) {
            const int ch = blk * 2 + c2;
            const int b = ch & 1;

            // ---- A fragments: shifted masked exp (base-2), fp16 ----
            const float* e2p = s_e2 + ch * 16;
            float2 e2a = *(const float2*)(e2p + cq);
            float2 e2b = *(const float2*)(e2p + cq + 8);
            unsigned Ah[4];
#pragma unroll
            for (int k = 0; k < 2; ++k) {
                const float e1v = e1r[k];
                float s0 = e1v + e2a.x; s0 = (s0 > 0.f ? s0 : LRA * s0) - mi[k];
                float s1 = e1v + e2a.y; s1 = (s1 > 0.f ? s1 : LRA * s1) - mi[k];
                float s2 = e1v + e2b.x; s2 = (s2 > 0.f ? s2 : LRA * s2) - mi[k];
                float s3 = e1v + e2b.y; s3 = (s3 > 0.f ? s3 : LRA * s3) - mi[k];
                float p0 = alo[b][k].x > 0 ? ex2a(s0) : 0.f;
                float p1 = alo[b][k].y > 0 ? ex2a(s1) : 0.f;
                float p2 = ahi[b][k].x > 0 ? ex2a(s2) : 0.f;
                float p3 = ahi[b][k].y > 0 ? ex2a(s3) : 0.f;
                Ah[k]     = cvt2h(p1, p0);
                Ah[k + 2] = cvt2h(p3, p2);
            }

            // ---- refill this buffer for chunk ch+2 (depth-2 window) ----
            if (ch + 2 < NCH) loadAdj(ch + 2);

            // ---- B fragments + products (+ ones-GEMM denominator) ----
            const uint32_t bo = (uint32_t)(s * BBUF + c2 * 32);
            unsigned Bh[8][2];
#pragma unroll
            for (int np = 0; np < 4; ++np)
                ldsm4(&Bh[2 * np][0], sBm + bo + np * (16 * BST));
#pragma unroll
            for (int n = 0; n < 8; ++n) mma_f16(acc[n], Ah, Bh[n][0], Bh[n][1]);
            mma_f16(accd, Ah, ONES, ONES);
        }
    }

    // ---- write partials ----
    if ((l & 3) == 0) {
        g_pden[split][i0 + w * 16 + rq]     = accd[0];
        g_pden[split][i0 + w * 16 + 8 + rq] = accd[2];
    }
    {
        const int row = i0 + w * 16 + rq;
#pragma unroll
        for (int n = 0; n < 8; ++n) {
            *(float2*)&g_pacc[split][row][n * 8 + cq]     = make_float2(acc[n][0], acc[n][1]);
            *(float2*)&g_pacc[split][row + 8][n * 8 + cq] = make_float2(acc[n][2], acc[n][3]);
        }
    }

    // ---- fused combine: last CTA of this row-tile reduces all splits ----
    __threadfence();
    __syncthreads();
    if (tid == 0)
        s_last = (atomicAdd(&g_cnt[blockIdx.x >> 3], 1) == JSPLITS - 1);
    __syncthreads();
    if (s_last) {
        __threadfence();
        for (int t = tid; t < 128 * 16; t += 256) {
            const int row = i0 + (t >> 4);
            const int c4 = (t & 15) * 4;
            float4 av = make_float4(0.f, 0.f, 0.f, 0.f);
            float den = 0.f;
#pragma unroll
            for (int sp = 0; sp < JSPLITS; ++sp) {
                float4 v = *(const float4*)&g_pacc[sp][row][c4];
                av.x += v.x; av.y += v.y; av.z += v.z; av.w += v.w;
                den += g_pden[sp][row];
            }
            if (den == 0.f) den = 1.f;
            float inv = 1.f / den;
            float4 o;
            o.x = av.x * inv; o.x = o.x > 0.f ? o.x : expm1f(o.x);
            o.y = av.y * inv; o.y = o.y > 0.f ? o.y : expm1f(o.y);
            o.z = av.z * inv; o.z = o.z > 0.f ? o.z : expm1f(o.z);
            o.w = av.w * inv; o.w = o.w > 0.f ? o.w : expm1f(o.w);
            *(float4*)&out[(size_t)row * NOUT + c4] = o;
        }
    }
}

// ---------------------------------------------------------------------------
extern "C" void kernel_launch(void* const* d_in, const int* in_sizes, int n_in,
                              void* d_out, int out_size) {
    const float* h   = (const float*)d_in[0];
    const float* W   = (const float*)d_in[1];
    const float* a   = (const float*)d_in[2];
    const int*   adj = (const int*)d_in[3];
    float* out = (float*)d_out;

    prep_w<<<32, 256>>>(W);
    wh_mma<<<128, 256>>>(h, a);
    e2max_kernel<<<1, 256>>>();
    attn_kernel<<<(NN / 128) * JSPLITS, 256>>>(adj, out);
}